// round 15
// baseline (speedup 1.0000x reference)
#include <cuda_runtime.h>
#include <cuda_bf16.h>

#define VSA_N    2048
#define VSA_BLK  512           // 16 warps
#define VSA_ROWS 16            // rows per block; lane l -> row (l & 15)

// ---------------------------------------------------------------------------
// Fused kernel. grid = (2048/16, B) = (128, 4) = 512 blocks x 16 warps.
//   * lane l owns row i = bx*16 + (l & 15): private Z,W accumulators
//   * j-stream s = warp*2 + (l >> 4): covers j in [s*64, s*64+64)
//
// DISCRIMINATING CHANGE vs R14: ONE MUFU per pair. Every ~19.5us variant so
// far used 2 MUFU/pair (sqrt + ex2) -- the only invariant resource across
// all plateau kernels. exp(eta) is replaced by an order-5 Taylor Horner
// chain in FFMA-imm form (rt=1), valid because eta = |qxk|/sqrt(N) <= ~0.8
// (validated numerically in R13, rel_err 7e-6).
//
// Math: T_i = q_i x (sum_j e_ij k_j) (bilinearity),
//       |q x k|^2 = |q|^2|k|^2 - (q.k)^2 (Lagrange),
//       k staged as k' = (k - mk)/sqrt(N), kk = |k'|^2; eta = sqrt(n2').
// ---------------------------------------------------------------------------
__global__ __launch_bounds__(VSA_BLK, 4)
void vsa_fused_kernel(const float* __restrict__ q,
                      const float* __restrict__ k,
                      const float* __restrict__ v,
                      float* __restrict__ out) {
    __shared__ float4 sk[VSA_N];           // 32 KB; reused for partials
    __shared__ float  red[VSA_BLK / 32][9];
    __shared__ float  means[9];

    const int tid  = threadIdx.x;
    const int b    = blockIdx.y;
    const int warp = tid >> 5;
    const int lane = tid & 31;

    const float* qb = q + (size_t)b * VSA_N * 3;
    const float* kb = k + (size_t)b * VSA_N * 3;
    const float* vb = v + (size_t)b * VSA_N * 3;

    // ---- Phase A: per-batch means (block-redundant, L2-resident) ----
    {
        float s[9];
#pragma unroll
        for (int c = 0; c < 9; c++) s[c] = 0.0f;

#pragma unroll
        for (int r = 0; r < VSA_N / VSA_BLK; r++) {
            const int o = (tid + r * VSA_BLK) * 3;
            s[0] += qb[o + 0]; s[1] += qb[o + 1]; s[2] += qb[o + 2];
            s[3] += kb[o + 0]; s[4] += kb[o + 1]; s[5] += kb[o + 2];
            s[6] += vb[o + 0]; s[7] += vb[o + 1]; s[8] += vb[o + 2];
        }
#pragma unroll
        for (int c = 0; c < 9; c++) {
#pragma unroll
            for (int off = 16; off > 0; off >>= 1)
                s[c] += __shfl_xor_sync(0xFFFFFFFFu, s[c], off);
        }
        if (lane == 0) {
#pragma unroll
            for (int c = 0; c < 9; c++) red[warp][c] = s[c];
        }
        __syncthreads();
        if (tid < 9) {
            float t = 0.0f;
#pragma unroll
            for (int w = 0; w < VSA_BLK / 32; w++) t += red[w][tid];
            means[tid] = t * (1.0f / (float)VSA_N);
        }
        __syncthreads();
    }

    const float mqx = means[0], mqy = means[1], mqz = means[2];
    const float mkx = means[3], mky = means[4], mkz = means[5];
    const float mvx = means[6], mvy = means[7], mvz = means[8];

    const float cs = 0.022097086912079612f;   // 1/sqrt(2048), natural exp

    // ---- Phase B: stage k' = (k-mk)*cs as float4 (xyz, |k'|^2) ----
#pragma unroll
    for (int r = 0; r < VSA_N / VSA_BLK; r++) {
        const int j = tid + r * VSA_BLK;
        const float kx = (kb[j * 3 + 0] - mkx) * cs;
        const float ky = (kb[j * 3 + 1] - mky) * cs;
        const float kz = (kb[j * 3 + 2] - mkz) * cs;
        const float kk = fmaf(kx, kx, fmaf(ky, ky, kz * kz));
        sk[j] = make_float4(kx, ky, kz, kk);
    }
    __syncthreads();

    // ---- Phase C: hot loop. Row = lane&15; j-stream = warp*2 + (lane>>4) ----
    const int row    = lane & 15;
    const int stream = warp * 2 + (lane >> 4);   // 0..31
    const int i      = blockIdx.x * VSA_ROWS + row;

    const float qx = qb[i * 3 + 0] - mqx;
    const float qy = qb[i * 3 + 1] - mqy;
    const float qz = qb[i * 3 + 2] - mqz;
    const float qq = fmaf(qx, qx, fmaf(qy, qy, qz * qz));

    float Z = 0.0f, Wx = 0.0f, Wy = 0.0f, Wz = 0.0f;

    const float4* pj = sk + stream * 64;
#pragma unroll 2
    for (int jj = 0; jj < 64; jj++) {
        const float4 f = pj[jj];   // half-warp broadcast
        const float dot = fmaf(qx, f.x, fmaf(qy, f.y, qz * f.z));
        const float n2 = fabsf(fmaf(-dot, dot, qq * f.w));
        float eta;
        asm("sqrt.approx.f32 %0, %1;" : "=f"(eta) : "f"(n2));  // ONLY MUFU
        // e = exp(eta), eta <= ~0.8: order-5 Taylor (FFMA-imm chain, rt=1)
        float t = fmaf(eta, 8.3333333e-3f, 4.1666668e-2f);     // 1/120, 1/24
        t = fmaf(eta, t, 0.16666667f);
        t = fmaf(eta, t, 0.5f);
        t = fmaf(eta, t, 1.0f);
        const float e = fmaf(eta, t, 1.0f);
        Z += e;
        Wx = fmaf(e, f.x, Wx);
        Wy = fmaf(e, f.y, Wy);
        Wz = fmaf(e, f.z, Wz);
    }

    // ---- Phase D: reduce 32 stream-partials per row ----
    __syncthreads();   // all warps done reading sk
    float4* part = sk;                       // part[stream*17 + row]
    part[stream * 17 + row] = make_float4(Z, Wx, Wy, Wz);
    __syncthreads();

    if (warp < VSA_ROWS) {
        const float4 p = part[lane * 17 + warp];
        float Zr = p.x, Wxr = p.y, Wyr = p.z, Wzr = p.w;
#pragma unroll
        for (int off = 16; off > 0; off >>= 1) {
            Zr  += __shfl_xor_sync(0xFFFFFFFFu, Zr,  off);
            Wxr += __shfl_xor_sync(0xFFFFFFFFu, Wxr, off);
            Wyr += __shfl_xor_sync(0xFFFFFFFFu, Wyr, off);
            Wzr += __shfl_xor_sync(0xFFFFFFFFu, Wzr, off);
        }

        if (lane == 0) {
            const int ir = blockIdx.x * VSA_ROWS + warp;
            const float qxr = qb[ir * 3 + 0] - mqx;
            const float qyr = qb[ir * 3 + 1] - mqy;
            const float qzr = qb[ir * 3 + 2] - mqz;
            // T' = q x W (= cs * T);  u = cross(T, v_c) / (Z * N)
            const float Tx = fmaf(qyr, Wzr, -qzr * Wyr);
            const float Ty = fmaf(qzr, Wxr, -qxr * Wzr);
            const float Tz = fmaf(qxr, Wyr, -qyr * Wxr);
            const float vx = vb[ir * 3 + 0] - mvx;
            const float vy = vb[ir * 3 + 1] - mvy;
            const float vz = vb[ir * 3 + 2] - mvz;
            const float inv = 1.0f / (Zr * (float)VSA_N * cs);
            float* o = out + ((size_t)b * VSA_N + ir) * 3;
            o[0] = fmaf(Ty, vz, -Tz * vy) * inv;
            o[1] = fmaf(Tz, vx, -Tx * vz) * inv;
            o[2] = fmaf(Tx, vy, -Ty * vx) * inv;
        }
    }
}

// ---------------------------------------------------------------------------
extern "C" void kernel_launch(void* const* d_in, const int* in_sizes, int n_in,
                              void* d_out, int out_size) {
    const float* q = (const float*)d_in[0];
    const float* k = (const float*)d_in[1];
    const float* v = (const float*)d_in[2];
    float* out = (float*)d_out;

    const int B = out_size / (VSA_N * 3);   // = 4

    dim3 grid(VSA_N / VSA_ROWS, B);         // (128, 4) = 512 blocks
    vsa_fused_kernel<<<grid, VSA_BLK>>>(q, k, v, out);
}